// round 10
// baseline (speedup 1.0000x reference)
#include <cuda_runtime.h>
#include <cuda_fp16.h>
#include <math.h>
#include <stdint.h>

#define BB 8
#define SS 2048
#define DD 768
#define HH 12
#define HD 64
#define M_ROWS (BB*SS)

// fp16 scratch (allocation-free __device__ globals)
__device__ __half g_X [M_ROWS*DD];          // x as fp16 [m][k]
__device__ __half g_W [3*DD*DD];            // qkv weights, n-major
__device__ __half g_Wp[DD*DD];              // Wp transposed: [n][k]
__device__ __half g_Q [BB*HH*SS*HD];
__device__ __half g_K [BB*HH*SS*HD];
__device__ __half g_V [BB*HH*SS*HD];
__device__ __half g_C [M_ROWS*DD];          // ctx fp16 [m][h*64+e]

// ---------------------------------------------------------------------------
// primitives
// ---------------------------------------------------------------------------
__device__ __forceinline__ uint32_t smem_u32(const void* p) {
    uint32_t a;
    asm("{ .reg .u64 t; cvta.to.shared.u64 t, %1; cvt.u32.u64 %0, t; }"
        : "=r"(a) : "l"(p));
    return a;
}
__device__ __forceinline__ void cp16(uint32_t dst, const void* src) {
    asm volatile("cp.async.cg.shared.global [%0], [%1], 16;" :: "r"(dst), "l"(src));
}
__device__ __forceinline__ void cp_commit() {
    asm volatile("cp.async.commit_group;" ::: "memory");
}
template<int N> __device__ __forceinline__ void cp_wait() {
    asm volatile("cp.async.wait_group %0;" :: "n"(N) : "memory");
}
__device__ __forceinline__ void ldsm4(uint32_t* r, uint32_t a) {
    asm volatile("ldmatrix.sync.aligned.m8n8.x4.shared.b16 {%0,%1,%2,%3}, [%4];"
        : "=r"(r[0]), "=r"(r[1]), "=r"(r[2]), "=r"(r[3]) : "r"(a));
}
__device__ __forceinline__ void ldsm4t(uint32_t* r, uint32_t a) {
    asm volatile("ldmatrix.sync.aligned.m8n8.x4.trans.shared.b16 {%0,%1,%2,%3}, [%4];"
        : "=r"(r[0]), "=r"(r[1]), "=r"(r[2]), "=r"(r[3]) : "r"(a));
}
__device__ __forceinline__ void mma16(float* c, const uint32_t* a,
                                      uint32_t b0, uint32_t b1) {
    asm volatile(
        "mma.sync.aligned.m16n8k16.row.col.f32.f16.f16.f32 "
        "{%0,%1,%2,%3},{%4,%5,%6,%7},{%8,%9},{%0,%1,%2,%3};"
        : "+f"(c[0]), "+f"(c[1]), "+f"(c[2]), "+f"(c[3])
        : "r"(a[0]), "r"(a[1]), "r"(a[2]), "r"(a[3]), "r"(b0), "r"(b1));
}
__device__ __forceinline__ uint32_t h2pack(float a, float b) {
    __half2 h = __floats2half2_rn(a, b);
    return *(uint32_t*)&h;
}

// ---------------------------------------------------------------------------
// prep kernels (fp32 -> fp16, weight transposes)
// ---------------------------------------------------------------------------
__global__ void prep_x(const float* __restrict__ x) {
    size_t idx = (size_t)blockIdx.x * 256 + threadIdx.x;
    const float4* s = (const float4*)x + idx * 2;
    float4 v0 = s[0], v1 = s[1];
    __half2 h0 = __floats2half2_rn(v0.x, v0.y);
    __half2 h1 = __floats2half2_rn(v0.z, v0.w);
    __half2 h2 = __floats2half2_rn(v1.x, v1.y);
    __half2 h3 = __floats2half2_rn(v1.z, v1.w);
    uint4 u;
    u.x = *(uint32_t*)&h0; u.y = *(uint32_t*)&h1;
    u.z = *(uint32_t*)&h2; u.w = *(uint32_t*)&h3;
    *(uint4*)&g_X[idx * 8] = u;
}

__global__ void prep_w(const float* __restrict__ Wq, const float* __restrict__ Wk,
                       const float* __restrict__ Wv) {
    int mh = blockIdx.x;
    int mat = mh / HH, h = mh % HH;
    const float* W = (mat == 0 ? Wq : mat == 1 ? Wk : Wv) + (size_t)h * DD * HD;
    __half* dst = g_W + ((size_t)mat * DD + h * HD) * DD;
    __shared__ float tile[32][HD + 1];
    int tid = threadIdx.x;
    for (int k0 = 0; k0 < DD; k0 += 32) {
        __syncthreads();
        #pragma unroll
        for (int it = 0; it < 8; it++) {
            int idx = tid + it * 256;
            int k = idx >> 6, e = idx & 63;
            tile[k][e] = W[(size_t)(k0 + k) * HD + e];
        }
        __syncthreads();
        #pragma unroll
        for (int it = 0; it < 8; it++) {
            int idx = tid + it * 256;
            int e = idx >> 5, k = idx & 31;
            dst[(size_t)e * DD + k0 + k] = __float2half(tile[k][e]);
        }
    }
}

__global__ void prep_wp(const float* __restrict__ Wp) {
    int n0 = blockIdx.x * 32, k0 = blockIdx.y * 32;
    __shared__ float tile[32][33];
    int tid = threadIdx.x;
    #pragma unroll
    for (int it = 0; it < 4; it++) {
        int idx = tid + it * 256;
        int k = idx >> 5, n = idx & 31;
        tile[k][n] = Wp[(size_t)(k0 + k) * DD + n0 + n];
    }
    __syncthreads();
    #pragma unroll
    for (int it = 0; it < 4; it++) {
        int idx = tid + it * 256;
        int n = idx >> 5, k = idx & 31;
        g_Wp[(size_t)(n0 + n) * DD + k0 + k] = __float2half(tile[k][n]);
    }
}

// ---------------------------------------------------------------------------
// GEMM: 128x256 block, 8 warps (2Mx4N) of 64x64, KC=32,
// 4-stage cp.async ring, one __syncthreads per k-tile.
// Row stride 40 halves (80B, conflict-free ldmatrix/cp.async).
// ---------------------------------------------------------------------------
#define GSTRIDE 40
#define ATILE (128 * GSTRIDE)
#define BTILE (256 * GSTRIDE)
#define GSTAGE (ATILE + BTILE)
#define GSM_BYTES (4 * GSTAGE * 2)        // 122880 B

__device__ __forceinline__ void gemm_stage(uint32_t aB, uint32_t bB,
                                           const __half* Ag, const __half* Bg,
                                           int t, int tid) {
    #pragma unroll
    for (int it = 0; it < 2; it++) {
        int idx = tid + it * 256;
        int r = idx >> 2, s = idx & 3;
        cp16(aB + (r * GSTRIDE + s * 8) * 2, Ag + (size_t)r * DD + t * 32 + s * 8);
    }
    #pragma unroll
    for (int it = 0; it < 4; it++) {
        int idx = tid + it * 256;
        int r = idx >> 2, s = idx & 3;
        cp16(bB + (r * GSTRIDE + s * 8) * 2, Bg + (size_t)r * DD + t * 32 + s * 8);
    }
}

__device__ __forceinline__ void gemm_compute(uint32_t aB, uint32_t bB,
                                             int lane, int wm, int wn,
                                             float acc[4][8][4]) {
    #pragma unroll
    for (int kst = 0; kst < 2; kst++) {
        uint32_t a[4][4], bf[8][2];
        #pragma unroll
        for (int mt = 0; mt < 4; mt++)
            ldsm4(a[mt], aB + ((wm + mt * 16 + (lane & 15)) * GSTRIDE
                               + kst * 16 + (lane >> 4) * 8) * 2);
        #pragma unroll
        for (int ng = 0; ng < 4; ng++) {
            uint32_t r[4];
            ldsm4(r, bB + ((wn + ng * 16 + (lane & 15)) * GSTRIDE
                           + kst * 16 + (lane >> 4) * 8) * 2);
            bf[ng * 2][0] = r[0]; bf[ng * 2][1] = r[2];
            bf[ng * 2 + 1][0] = r[1]; bf[ng * 2 + 1][1] = r[3];
        }
        #pragma unroll
        for (int mt = 0; mt < 4; mt++)
            #pragma unroll
            for (int nt = 0; nt < 8; nt++)
                mma16(acc[mt][nt], a[mt], bf[nt][0], bf[nt][1]);
    }
}

#define GEMM_MAINLOOP(Ag, Bg)                                                  \
    uint32_t aS[4], bS[4];                                                     \
    {                                                                          \
        uint32_t base = smem_u32(dynsm);                                       \
        _Pragma("unroll")                                                      \
        for (int s = 0; s < 4; s++) {                                          \
            aS[s] = base + s * GSTAGE * 2;                                     \
            bS[s] = aS[s] + ATILE * 2;                                         \
        }                                                                      \
    }                                                                          \
    float acc[4][8][4] = {};                                                   \
    _Pragma("unroll")                                                          \
    for (int s = 0; s < 3; s++) {                                              \
        gemm_stage(aS[s], bS[s], Ag, Bg, s, tid);                              \
        cp_commit();                                                           \
    }                                                                          \
    for (int t = 0; t < 24; t++) {                                             \
        cp_wait<2>();                                                          \
        __syncthreads();                                                       \
        if (t + 3 < 24) gemm_stage(aS[(t+3)&3], bS[(t+3)&3], Ag, Bg, t+3, tid);\
        cp_commit();                                                           \
        gemm_compute(aS[t & 3], bS[t & 3], lane, wm, wn, acc);                 \
    }

// ---------------------------------------------------------------------------
// Kernel 1: fused QKV GEMM. C[16384, 2304] = X @ Wn^T. Grid (9, 128).
// ---------------------------------------------------------------------------
__global__ __launch_bounds__(256, 1)
void qkv_hmma(const float* __restrict__ bq, const float* __restrict__ bk,
              const float* __restrict__ bv) {
    extern __shared__ __half dynsm[];
    int bx = blockIdx.x;
    int m0 = blockIdx.y * 128;
    int tid = threadIdx.x, warp = tid >> 5, lane = tid & 31;
    int g = lane >> 2, t4 = lane & 3;
    int wm = (warp >> 2) * 64, wn = (warp & 3) * 64;

    const __half* Ag = g_X + (size_t)m0 * DD;
    const __half* Bg = g_W + (size_t)bx * 256 * DD;

    GEMM_MAINLOOP(Ag, Bg)

    #pragma unroll
    for (int nt = 0; nt < 8; nt++) {
        int n_glob = bx * 256 + wn + nt * 8 + 2 * t4;
        int matIdx = n_glob / DD;
        int rem    = n_glob % DD;
        int h = rem >> 6, e = rem & 63;
        __half* Out = matIdx == 0 ? g_Q : matIdx == 1 ? g_K : g_V;
        const float* bias = matIdx == 0 ? bq : matIdx == 1 ? bk : bv;
        float2 bb = *(const float2*)&bias[h * HD + e];
        #pragma unroll
        for (int mt = 0; mt < 4; mt++) {
            int m = m0 + wm + mt * 16 + g;
            int b = m >> 11, s = m & 2047;
            size_t base0 = (((size_t)b * HH + h) * SS + s) * HD + e;
            *(__half2*)&Out[base0] =
                __floats2half2_rn(acc[mt][nt][0] + bb.x, acc[mt][nt][1] + bb.y);
            *(__half2*)&Out[base0 + 8 * HD] =
                __floats2half2_rn(acc[mt][nt][2] + bb.x, acc[mt][nt][3] + bb.y);
        }
    }
}

// ---------------------------------------------------------------------------
// Kernel 3: output projection. out[16384, 768] = ctx @ Wp^T + bp. Grid (3, 128).
// ---------------------------------------------------------------------------
__global__ __launch_bounds__(256, 1)
void proj_hmma(const float* __restrict__ bp, float* __restrict__ out) {
    extern __shared__ __half dynsm[];
    int n0 = blockIdx.x * 256;
    int m0 = blockIdx.y * 128;
    int tid = threadIdx.x, warp = tid >> 5, lane = tid & 31;
    int g = lane >> 2, t4 = lane & 3;
    int wm = (warp >> 2) * 64, wn = (warp & 3) * 64;

    const __half* Ag = g_C + (size_t)m0 * DD;
    const __half* Bg = g_Wp + (size_t)n0 * DD;

    GEMM_MAINLOOP(Ag, Bg)

    #pragma unroll
    for (int nt = 0; nt < 8; nt++) {
        int n = n0 + wn + nt * 8 + 2 * t4;
        float2 bb = *(const float2*)&bp[n];
        #pragma unroll
        for (int mt = 0; mt < 4; mt++) {
            int m = m0 + wm + mt * 16 + g;
            float2 o0 = {acc[mt][nt][0] + bb.x, acc[mt][nt][1] + bb.y};
            float2 o1 = {acc[mt][nt][2] + bb.x, acc[mt][nt][3] + bb.y};
            *(float2*)&out[(size_t)m * DD + n]       = o0;
            *(float2*)&out[(size_t)(m + 8) * DD + n] = o1;
        }
    }
}

// ---------------------------------------------------------------------------
// Kernel 2: flash attention, fp16 mma. BR=256, BC=64, 8 warps x 32 q-rows.
// Q register-resident; P register-repacked. 3-stage KV cp.async ring.
// Row stride 72 halves (144B, conflict-free).
// ---------------------------------------------------------------------------
#define ASTRIDE 72
#define KVSZ (64 * ASTRIDE)
#define QSM  (256 * ASTRIDE)
#define ATT_SM_BYTES ((QSM + 6 * KVSZ) * 2)    // 92160 B

__global__ __launch_bounds__(256, 1)
void attn_hmma() {
    extern __shared__ __half sh[];
    __half* Qs = sh;                    // 256 x 72
    __half* Ks = sh + QSM;              // 3 x 64 x 72
    __half* Vs = Ks + 3 * KVSZ;         // 3 x 64 x 72

    int bh = blockIdx.y, q0 = blockIdx.x * 256;
    const __half* Qg = g_Q + (size_t)bh * SS * HD;
    const __half* Kg = g_K + (size_t)bh * SS * HD;
    const __half* Vg = g_V + (size_t)bh * SS * HD;
    int b = bh / HH, h = bh % HH;

    int tid = threadIdx.x, warp = tid >> 5, lane = tid & 31;
    int g = lane >> 2, t4 = lane & 3;
    int wm = warp * 32;

    uint32_t qB = smem_u32(Qs), kB = smem_u32(Ks), vB = smem_u32(Vs);

    // group 0: Q (256 rows)
    #pragma unroll
    for (int it = 0; it < 8; it++) {
        int idx = tid + it * 256;
        int r = idx >> 3, s = idx & 7;
        cp16(qB + (r * ASTRIDE + s * 8) * 2, Qg + (size_t)(q0 + r) * HD + s * 8);
    }
    cp_commit();

    #define STAGE_KV(kc, buf) do {                                              \
        const __half* Ksrc = Kg + (size_t)(kc) * 64 * HD;                       \
        const __half* Vsrc = Vg + (size_t)(kc) * 64 * HD;                       \
        uint32_t kd = kB + (buf) * KVSZ * 2, vd = vB + (buf) * KVSZ * 2;        \
        _Pragma("unroll")                                                       \
        for (int it = 0; it < 2; it++) {                                        \
            int idx = tid + it * 256;                                           \
            int r = idx >> 3, s = idx & 7;                                      \
            cp16(kd + (r * ASTRIDE + s * 8) * 2, Ksrc + (size_t)r * HD + s * 8);\
            cp16(vd + (r * ASTRIDE + s * 8) * 2, Vsrc + (size_t)r * HD + s * 8);\
        }                                                                       \
        cp_commit();                                                            \
    } while (0)

    STAGE_KV(0, 0);     // group 1
    STAGE_KV(1, 1);     // group 2

    cp_wait<2>();       // group 0 (Q) complete
    __syncthreads();

    // Q fragments: 2 m-tiles x 4 k-steps, register-resident
    uint32_t qa[2][4][4];
    #pragma unroll
    for (int mt = 0; mt < 2; mt++)
        #pragma unroll
        for (int kst = 0; kst < 4; kst++)
            ldsm4(qa[mt][kst], qB + ((wm + mt * 16 + (lane & 15)) * ASTRIDE
                                     + kst * 16 + (lane >> 4) * 8) * 2);

    float o[2][8][4] = {};
    float m_i[2][2] = {{-1e30f, -1e30f}, {-1e30f, -1e30f}};
    float l_i[2][2] = {{0.f, 0.f}, {0.f, 0.f}};
    const float inv_scale = 1.0f / (8.0f + 1e-6f);   // 1/(sqrt(64)+EPS)

    for (int kc = 0; kc < 32; kc++) {
        cp_wait<1>();        // KV(kc) complete
        __syncthreads();
        if (kc + 2 < 32) STAGE_KV(kc + 2, (kc + 2) % 3);
        else cp_commit();    // uniform group accounting

        int bf = kc % 3;
        uint32_t kb = kB + bf * KVSZ * 2;
        uint32_t vb = vB + bf * KVSZ * 2;

        // scores for both m-tiles: K frags loaded once, reused across mt
        float sc[2][8][4] = {};
        #pragma unroll
        for (int kst = 0; kst < 4; kst++) {
            #pragma unroll
            for (int cp = 0; cp < 4; cp++) {
                uint32_t r[4];
                ldsm4(r, kb + ((cp * 16 + (lane & 15)) * ASTRIDE
                               + kst * 16 + (lane >> 4) * 8) * 2);
                #pragma unroll
                for (int mt = 0; mt < 2; mt++) {
                    mma16(sc[mt][cp * 2],     qa[mt][kst], r[0], r[2]);
                    mma16(sc[mt][cp * 2 + 1], qa[mt][kst], r[1], r[3]);
                }
            }
        }

        // online softmax per m-tile (rows g, g+8 in each)
        #pragma unroll
        for (int mt = 0; mt < 2; mt++) {
            float rmax0 = -1e30f, rmax1 = -1e30f;
            #pragma unroll
            for (int nt = 0; nt < 8; nt++) {
                #pragma unroll
                for (int j = 0; j < 4; j++) sc[mt][nt][j] *= inv_scale;
                rmax0 = fmaxf(rmax0, fmaxf(sc[mt][nt][0], sc[mt][nt][1]));
                rmax1 = fmaxf(rmax1, fmaxf(sc[mt][nt][2], sc[mt][nt][3]));
            }
            #pragma unroll
            for (int off = 1; off <= 2; off <<= 1) {
                rmax0 = fmaxf(rmax0, __shfl_xor_sync(0xffffffffu, rmax0, off, 4));
                rmax1 = fmaxf(rmax1, __shfl_xor_sync(0xffffffffu, rmax1, off, 4));
            }
            float mn0 = fmaxf(m_i[mt][0], rmax0);
            float mn1 = fmaxf(m_i[mt][1], rmax1);
            float fac0 = __expf(m_i[mt][0] - mn0);
            float fac1 = __expf(m_i[mt][1] - mn1);
            m_i[mt][0] = mn0; m_i[mt][1] = mn1;

            float rs0 = 0.f, rs1 = 0.f;
            #pragma unroll
            for (int nt = 0; nt < 8; nt++) {
                sc[mt][nt][0] = __expf(sc[mt][nt][0] - mn0);
                sc[mt][nt][1] = __expf(sc[mt][nt][1] - mn0);
                sc[mt][nt][2] = __expf(sc[mt][nt][2] - mn1);
                sc[mt][nt][3] = __expf(sc[mt][nt][3] - mn1);
                rs0 += sc[mt][nt][0] + sc[mt][nt][1];
                rs1 += sc[mt][nt][2] + sc[mt][nt][3];
            }
            #pragma unroll
            for (int off = 1; off <= 2; off <<= 1) {
                rs0 += __shfl_xor_sync(0xffffffffu, rs0, off, 4);
                rs1 += __shfl_xor_sync(0xffffffffu, rs1, off, 4);
            }
            l_i[mt][0] = l_i[mt][0] * fac0 + rs0;
            l_i[mt][1] = l_i[mt][1] * fac1 + rs1;
            #pragma unroll
            for (int et = 0; et < 8; et++) {
                o[mt][et][0] *= fac0; o[mt][et][1] *= fac0;
                o[mt][et][2] *= fac1; o[mt][et][3] *= fac1;
            }
        }

        // O += P @ V ; V frags loaded once per (kst,eb), reused across mt
        #pragma unroll
        for (int kst = 0; kst < 4; kst++) {
            uint32_t pa[2][4];
            #pragma unroll
            for (int mt = 0; mt < 2; mt++) {
                pa[mt][0] = h2pack(sc[mt][2*kst][0],   sc[mt][2*kst][1]);
                pa[mt][1] = h2pack(sc[mt][2*kst][2],   sc[mt][2*kst][3]);
                pa[mt][2] = h2pack(sc[mt][2*kst+1][0], sc[mt][2*kst+1][1]);
                pa[mt][3] = h2pack(sc[mt][2*kst+1][2], sc[mt][2*kst+1][3]);
            }
            #pragma unroll
            for (int eb = 0; eb < 4; eb++) {
                uint32_t r[4];
                ldsm4t(r, vb + ((kst * 16 + (lane & 15)) * ASTRIDE
                                + eb * 16 + (lane >> 4) * 8) * 2);
                #pragma unroll
                for (int mt = 0; mt < 2; mt++) {
                    mma16(o[mt][eb * 2],     pa[mt], r[0], r[1]);
                    mma16(o[mt][eb * 2 + 1], pa[mt], r[2], r[3]);
                }
            }
        }
    }

    // normalize + store ctx fp16 into [m][768]
    #pragma unroll
    for (int mt = 0; mt < 2; mt++) {
        float il0 = 1.0f / l_i[mt][0], il1 = 1.0f / l_i[mt][1];
        int s0 = q0 + wm + mt * 16 + g;
        size_t row0 = ((size_t)b * SS + s0) * DD + h * HD;
        #pragma unroll
        for (int et = 0; et < 8; et++) {
            int c = et * 8 + 2 * t4;
            *(__half2*)&g_C[row0 + c] =
                __floats2half2_rn(o[mt][et][0] * il0, o[mt][et][1] * il0);
            *(__half2*)&g_C[row0 + 8 * DD + c] =
                __floats2half2_rn(o[mt][et][2] * il1, o[mt][et][3] * il1);
        }
    }
}

// ---------------------------------------------------------------------------
extern "C" void kernel_launch(void* const* d_in, const int* in_sizes, int n_in,
                              void* d_out, int out_size) {
    const float* x  = (const float*)d_in[0];
    const float* Wq = (const float*)d_in[1];
    const float* bq = (const float*)d_in[2];
    const float* Wk = (const float*)d_in[3];
    const float* bk = (const float*)d_in[4];
    const float* Wv = (const float*)d_in[5];
    const float* bv = (const float*)d_in[6];
    const float* Wp = (const float*)d_in[7];
    const float* bp = (const float*)d_in[8];
    float* out = (float*)d_out;

    prep_x<<<M_ROWS * DD / (8 * 256), 256>>>(x);
    prep_w<<<36, 256>>>(Wq, Wk, Wv);
    prep_wp<<<dim3(DD / 32, DD / 32), 256>>>(Wp);

    cudaFuncSetAttribute(qkv_hmma, cudaFuncAttributeMaxDynamicSharedMemorySize,
                         GSM_BYTES);
    qkv_hmma<<<dim3(3 * DD / 256, M_ROWS / 128), 256, GSM_BYTES>>>(bq, bk, bv);

    cudaFuncSetAttribute(attn_hmma, cudaFuncAttributeMaxDynamicSharedMemorySize,
                         ATT_SM_BYTES);
    attn_hmma<<<dim3(SS / 256, BB * HH), 256, ATT_SM_BYTES>>>();

    cudaFuncSetAttribute(proj_hmma, cudaFuncAttributeMaxDynamicSharedMemorySize,
                         GSM_BYTES);
    proj_hmma<<<dim3(DD / 256, M_ROWS / 128), 256, GSM_BYTES>>>(bp, out);
}

// round 11
// speedup vs baseline: 1.0264x; 1.0264x over previous
#include <cuda_runtime.h>
#include <cuda_fp16.h>
#include <math.h>
#include <stdint.h>

#define BB 8
#define SS 2048
#define DD 768
#define HH 12
#define HD 64
#define M_ROWS (BB*SS)

// fp16 scratch (allocation-free __device__ globals)
__device__ __half g_X [M_ROWS*DD];          // x as fp16 [m][k]
__device__ __half g_W [3*DD*DD];            // qkv weights, n-major
__device__ __half g_Wp[DD*DD];              // Wp transposed: [n][k]
__device__ __half g_Q [BB*HH*SS*HD];
__device__ __half g_K [BB*HH*SS*HD];
__device__ __half g_V [BB*HH*SS*HD];
__device__ __half g_C [M_ROWS*DD];          // ctx fp16 [m][h*64+e]

// ---------------------------------------------------------------------------
// primitives
// ---------------------------------------------------------------------------
__device__ __forceinline__ uint32_t smem_u32(const void* p) {
    uint32_t a;
    asm("{ .reg .u64 t; cvta.to.shared.u64 t, %1; cvt.u32.u64 %0, t; }"
        : "=r"(a) : "l"(p));
    return a;
}
__device__ __forceinline__ void cp16(uint32_t dst, const void* src) {
    asm volatile("cp.async.cg.shared.global [%0], [%1], 16;" :: "r"(dst), "l"(src));
}
__device__ __forceinline__ void cp_commit() {
    asm volatile("cp.async.commit_group;" ::: "memory");
}
template<int N> __device__ __forceinline__ void cp_wait() {
    asm volatile("cp.async.wait_group %0;" :: "n"(N) : "memory");
}
__device__ __forceinline__ void ldsm4(uint32_t* r, uint32_t a) {
    asm volatile("ldmatrix.sync.aligned.m8n8.x4.shared.b16 {%0,%1,%2,%3}, [%4];"
        : "=r"(r[0]), "=r"(r[1]), "=r"(r[2]), "=r"(r[3]) : "r"(a));
}
__device__ __forceinline__ void ldsm4t(uint32_t* r, uint32_t a) {
    asm volatile("ldmatrix.sync.aligned.m8n8.x4.trans.shared.b16 {%0,%1,%2,%3}, [%4];"
        : "=r"(r[0]), "=r"(r[1]), "=r"(r[2]), "=r"(r[3]) : "r"(a));
}
// fp32-accumulate HMMA
__device__ __forceinline__ void mma16(float* c, const uint32_t* a,
                                      uint32_t b0, uint32_t b1) {
    asm volatile(
        "mma.sync.aligned.m16n8k16.row.col.f32.f16.f16.f32 "
        "{%0,%1,%2,%3},{%4,%5,%6,%7},{%8,%9},{%0,%1,%2,%3};"
        : "+f"(c[0]), "+f"(c[1]), "+f"(c[2]), "+f"(c[3])
        : "r"(a[0]), "r"(a[1]), "r"(a[2]), "r"(a[3]), "r"(b0), "r"(b1));
}
// fp16-accumulate HMMA (QK^T only — rate experiment)
__device__ __forceinline__ void mma16h(uint32_t* c, const uint32_t* a,
                                       uint32_t b0, uint32_t b1) {
    asm volatile(
        "mma.sync.aligned.m16n8k16.row.col.f16.f16.f16.f16 "
        "{%0,%1},{%2,%3,%4,%5},{%6,%7},{%0,%1};"
        : "+r"(c[0]), "+r"(c[1])
        : "r"(a[0]), "r"(a[1]), "r"(a[2]), "r"(a[3]), "r"(b0), "r"(b1));
}
__device__ __forceinline__ uint32_t h2pack(float a, float b) {
    __half2 h = __floats2half2_rn(a, b);
    return *(uint32_t*)&h;
}

// ---------------------------------------------------------------------------
// prep kernels (fp32 -> fp16, weight transposes)
// ---------------------------------------------------------------------------
__global__ void prep_x(const float* __restrict__ x) {
    size_t idx = (size_t)blockIdx.x * 256 + threadIdx.x;
    const float4* s = (const float4*)x + idx * 2;
    float4 v0 = s[0], v1 = s[1];
    __half2 h0 = __floats2half2_rn(v0.x, v0.y);
    __half2 h1 = __floats2half2_rn(v0.z, v0.w);
    __half2 h2 = __floats2half2_rn(v1.x, v1.y);
    __half2 h3 = __floats2half2_rn(v1.z, v1.w);
    uint4 u;
    u.x = *(uint32_t*)&h0; u.y = *(uint32_t*)&h1;
    u.z = *(uint32_t*)&h2; u.w = *(uint32_t*)&h3;
    *(uint4*)&g_X[idx * 8] = u;
}

__global__ void prep_w(const float* __restrict__ Wq, const float* __restrict__ Wk,
                       const float* __restrict__ Wv) {
    int mh = blockIdx.x;
    int mat = mh / HH, h = mh % HH;
    const float* W = (mat == 0 ? Wq : mat == 1 ? Wk : Wv) + (size_t)h * DD * HD;
    __half* dst = g_W + ((size_t)mat * DD + h * HD) * DD;
    __shared__ float tile[32][HD + 1];
    int tid = threadIdx.x;
    for (int k0 = 0; k0 < DD; k0 += 32) {
        __syncthreads();
        #pragma unroll
        for (int it = 0; it < 8; it++) {
            int idx = tid + it * 256;
            int k = idx >> 6, e = idx & 63;
            tile[k][e] = W[(size_t)(k0 + k) * HD + e];
        }
        __syncthreads();
        #pragma unroll
        for (int it = 0; it < 8; it++) {
            int idx = tid + it * 256;
            int e = idx >> 5, k = idx & 31;
            dst[(size_t)e * DD + k0 + k] = __float2half(tile[k][e]);
        }
    }
}

__global__ void prep_wp(const float* __restrict__ Wp) {
    int n0 = blockIdx.x * 32, k0 = blockIdx.y * 32;
    __shared__ float tile[32][33];
    int tid = threadIdx.x;
    #pragma unroll
    for (int it = 0; it < 4; it++) {
        int idx = tid + it * 256;
        int k = idx >> 5, n = idx & 31;
        tile[k][n] = Wp[(size_t)(k0 + k) * DD + n0 + n];
    }
    __syncthreads();
    #pragma unroll
    for (int it = 0; it < 4; it++) {
        int idx = tid + it * 256;
        int n = idx >> 5, k = idx & 31;
        g_Wp[(size_t)(n0 + n) * DD + k0 + k] = __float2half(tile[k][n]);
    }
}

// ---------------------------------------------------------------------------
// GEMM (Round-8 config): 128x128 block, 8 warps (2Mx4N) of 64x32, KC=32,
// double-buffered cp.async. Row stride 40 halves (80B, conflict-free).
// ---------------------------------------------------------------------------
#define GSTRIDE 40

__device__ __forceinline__ void gemm_stage(uint32_t aB, uint32_t bB,
                                           const __half* Ag, const __half* Bg,
                                           int t, int tid) {
    #pragma unroll
    for (int it = 0; it < 2; it++) {
        int idx = tid + it * 256;
        int r = idx >> 2, s = idx & 3;
        cp16(aB + (r * GSTRIDE + s * 8) * 2, Ag + (size_t)r * DD + t * 32 + s * 8);
        cp16(bB + (r * GSTRIDE + s * 8) * 2, Bg + (size_t)r * DD + t * 32 + s * 8);
    }
    cp_commit();
}

__device__ __forceinline__ void gemm_compute(uint32_t aB, uint32_t bB,
                                             int lane, int wm, int wn,
                                             float acc[4][4][4]) {
    #pragma unroll
    for (int kst = 0; kst < 2; kst++) {
        uint32_t a[4][4], bf[4][2];
        #pragma unroll
        for (int mt = 0; mt < 4; mt++)
            ldsm4(a[mt], aB + ((wm + mt * 16 + (lane & 15)) * GSTRIDE
                               + kst * 16 + (lane >> 4) * 8) * 2);
        #pragma unroll
        for (int np = 0; np < 2; np++) {
            uint32_t r[4];
            ldsm4(r, bB + ((wn + np * 16 + (lane & 15)) * GSTRIDE
                           + kst * 16 + (lane >> 4) * 8) * 2);
            bf[np * 2][0] = r[0]; bf[np * 2][1] = r[2];
            bf[np * 2 + 1][0] = r[1]; bf[np * 2 + 1][1] = r[3];
        }
        #pragma unroll
        for (int mt = 0; mt < 4; mt++)
            #pragma unroll
            for (int nt = 0; nt < 4; nt++)
                mma16(acc[mt][nt], a[mt], bf[nt][0], bf[nt][1]);
    }
}

// ---------------------------------------------------------------------------
// Kernel 1: fused QKV GEMM. C[16384, 2304] = X @ Wn^T. Grid (18, 128).
// ---------------------------------------------------------------------------
__global__ __launch_bounds__(256, 2)
void qkv_hmma(const float* __restrict__ bq, const float* __restrict__ bk,
              const float* __restrict__ bv) {
    __shared__ __half Asm[2][128 * GSTRIDE];
    __shared__ __half Bsm[2][128 * GSTRIDE];
    int bx = blockIdx.x;
    int m0 = blockIdx.y * 128;
    int tid = threadIdx.x, warp = tid >> 5, lane = tid & 31;
    int g = lane >> 2, t4 = lane & 3;
    int wm = (warp >> 2) * 64, wn = (warp & 3) * 32;

    const __half* Ag = g_X + (size_t)m0 * DD;
    const __half* Bg = g_W + (size_t)bx * 128 * DD;
    uint32_t aB[2] = {smem_u32(Asm[0]), smem_u32(Asm[1])};
    uint32_t bB[2] = {smem_u32(Bsm[0]), smem_u32(Bsm[1])};

    float acc[4][4][4] = {};
    gemm_stage(aB[0], bB[0], Ag, Bg, 0, tid);
    for (int t = 0; t < 24; t++) {
        if (t < 23) { gemm_stage(aB[(t+1)&1], bB[(t+1)&1], Ag, Bg, t + 1, tid);
                      cp_wait<1>(); }
        else cp_wait<0>();
        __syncthreads();
        gemm_compute(aB[t & 1], bB[t & 1], lane, wm, wn, acc);
        __syncthreads();
    }

    int matIdx  = (bx * 128) / DD;
    int remBase = (bx * 128) % DD + wn;
    __half* Out = matIdx == 0 ? g_Q : matIdx == 1 ? g_K : g_V;
    const float* bias = matIdx == 0 ? bq : matIdx == 1 ? bk : bv;
    #pragma unroll
    for (int nt = 0; nt < 4; nt++) {
        int rem = remBase + nt * 8 + 2 * t4;
        int h = rem >> 6, e = rem & 63;
        float2 bb = *(const float2*)&bias[h * HD + e];
        #pragma unroll
        for (int mt = 0; mt < 4; mt++) {
            int m = m0 + wm + mt * 16 + g;
            int b = m >> 11, s = m & 2047;
            size_t base0 = (((size_t)b * HH + h) * SS + s) * HD + e;
            *(__half2*)&Out[base0] =
                __floats2half2_rn(acc[mt][nt][0] + bb.x, acc[mt][nt][1] + bb.y);
            *(__half2*)&Out[base0 + 8 * HD] =
                __floats2half2_rn(acc[mt][nt][2] + bb.x, acc[mt][nt][3] + bb.y);
        }
    }
}

// ---------------------------------------------------------------------------
// Kernel 3: output projection. out[16384, 768] = ctx @ Wp^T + bp. Grid (6, 128).
// ---------------------------------------------------------------------------
__global__ __launch_bounds__(256, 2)
void proj_hmma(const float* __restrict__ bp, float* __restrict__ out) {
    __shared__ __half Asm[2][128 * GSTRIDE];
    __shared__ __half Bsm[2][128 * GSTRIDE];
    int n0 = blockIdx.x * 128;
    int m0 = blockIdx.y * 128;
    int tid = threadIdx.x, warp = tid >> 5, lane = tid & 31;
    int g = lane >> 2, t4 = lane & 3;
    int wm = (warp >> 2) * 64, wn = (warp & 3) * 32;

    const __half* Ag = g_C + (size_t)m0 * DD;
    const __half* Bg = g_Wp + (size_t)n0 * DD;
    uint32_t aB[2] = {smem_u32(Asm[0]), smem_u32(Asm[1])};
    uint32_t bB[2] = {smem_u32(Bsm[0]), smem_u32(Bsm[1])};

    float acc[4][4][4] = {};
    gemm_stage(aB[0], bB[0], Ag, Bg, 0, tid);
    for (int t = 0; t < 24; t++) {
        if (t < 23) { gemm_stage(aB[(t+1)&1], bB[(t+1)&1], Ag, Bg, t + 1, tid);
                      cp_wait<1>(); }
        else cp_wait<0>();
        __syncthreads();
        gemm_compute(aB[t & 1], bB[t & 1], lane, wm, wn, acc);
        __syncthreads();
    }

    #pragma unroll
    for (int nt = 0; nt < 4; nt++) {
        int n = n0 + wn + nt * 8 + 2 * t4;
        float2 bb = *(const float2*)&bp[n];
        #pragma unroll
        for (int mt = 0; mt < 4; mt++) {
            int m = m0 + wm + mt * 16 + g;
            float2 o0 = {acc[mt][nt][0] + bb.x, acc[mt][nt][1] + bb.y};
            float2 o1 = {acc[mt][nt][2] + bb.x, acc[mt][nt][3] + bb.y};
            *(float2*)&out[(size_t)m * DD + n]       = o0;
            *(float2*)&out[(size_t)(m + 8) * DD + n] = o1;
        }
    }
}

// ---------------------------------------------------------------------------
// Kernel 2: flash attention. BR=128, BC=64, 8 warps x 16 q-rows.
// QK^T uses f16-accumulate HMMA (rate experiment); PV stays f32-accumulate.
// Q register-resident; P register-repacked. 3-stage KV cp.async ring.
// ---------------------------------------------------------------------------
#define ASTRIDE 72
#define KVSZ (64 * ASTRIDE)
#define ATT_SM_BYTES ((128 * ASTRIDE + 6 * KVSZ) * 2)

__global__ __launch_bounds__(256, 2)
void attn_hmma() {
    extern __shared__ __half sh[];
    __half* Qs = sh;                    // 128 x 72
    __half* Ks = sh + 128 * ASTRIDE;    // 3 x 64 x 72
    __half* Vs = Ks + 3 * KVSZ;         // 3 x 64 x 72

    int bh = blockIdx.y, q0 = blockIdx.x * 128;
    const __half* Qg = g_Q + (size_t)bh * SS * HD;
    const __half* Kg = g_K + (size_t)bh * SS * HD;
    const __half* Vg = g_V + (size_t)bh * SS * HD;
    int b = bh / HH, h = bh % HH;

    int tid = threadIdx.x, warp = tid >> 5, lane = tid & 31;
    int g = lane >> 2, t4 = lane & 3;
    int wm = warp * 16;

    uint32_t qB = smem_u32(Qs), kB = smem_u32(Ks), vB = smem_u32(Vs);

    // group 0: Q
    #pragma unroll
    for (int it = 0; it < 4; it++) {
        int idx = tid + it * 256;
        int r = idx >> 3, s = idx & 7;
        cp16(qB + (r * ASTRIDE + s * 8) * 2, Qg + (size_t)(q0 + r) * HD + s * 8);
    }
    cp_commit();

    #define STAGE_KV(kc, buf) do {                                              \
        const __half* Ksrc = Kg + (size_t)(kc) * 64 * HD;                       \
        const __half* Vsrc = Vg + (size_t)(kc) * 64 * HD;                       \
        uint32_t kd = kB + (buf) * KVSZ * 2, vd = vB + (buf) * KVSZ * 2;        \
        _Pragma("unroll")                                                       \
        for (int it = 0; it < 2; it++) {                                        \
            int idx = tid + it * 256;                                           \
            int r = idx >> 3, s = idx & 7;                                      \
            cp16(kd + (r * ASTRIDE + s * 8) * 2, Ksrc + (size_t)r * HD + s * 8);\
            cp16(vd + (r * ASTRIDE + s * 8) * 2, Vsrc + (size_t)r * HD + s * 8);\
        }                                                                       \
        cp_commit();                                                            \
    } while (0)

    STAGE_KV(0, 0);     // group 1
    STAGE_KV(1, 1);     // group 2

    cp_wait<2>();       // group 0 (Q) complete
    __syncthreads();

    uint32_t qa[4][4];
    #pragma unroll
    for (int kst = 0; kst < 4; kst++)
        ldsm4(qa[kst], qB + ((wm + (lane & 15)) * ASTRIDE
                             + kst * 16 + (lane >> 4) * 8) * 2);

    float o[8][4] = {};
    float m_i[2] = {-1e30f, -1e30f};
    float l_i[2] = {0.f, 0.f};
    const float inv_scale = 1.0f / (8.0f + 1e-6f);   // 1/(sqrt(64)+EPS)

    for (int kc = 0; kc < 32; kc++) {
        cp_wait<1>();        // KV(kc) complete
        __syncthreads();
        if (kc + 2 < 32) STAGE_KV(kc + 2, (kc + 2) % 3);
        else cp_commit();    // uniform group accounting

        int bf = kc % 3;
        uint32_t kb = kB + bf * KVSZ * 2;
        uint32_t vb = vB + bf * KVSZ * 2;

        // scores via f16-accumulate HMMA (8 n8-tiles over 64 keys)
        uint32_t sch[8][2];
        #pragma unroll
        for (int nt = 0; nt < 8; nt++) { sch[nt][0] = 0u; sch[nt][1] = 0u; }
        #pragma unroll
        for (int kst = 0; kst < 4; kst++) {
            #pragma unroll
            for (int cp = 0; cp < 4; cp++) {
                uint32_t r[4];
                ldsm4(r, kb + ((cp * 16 + (lane & 15)) * ASTRIDE
                               + kst * 16 + (lane >> 4) * 8) * 2);
                mma16h(sch[cp * 2],     qa[kst], r[0], r[2]);
                mma16h(sch[cp * 2 + 1], qa[kst], r[1], r[3]);
            }
        }
        // unpack f16 scores -> f32
        float sc[8][4];
        #pragma unroll
        for (int nt = 0; nt < 8; nt++) {
            float2 lo = __half22float2(*(__half2*)&sch[nt][0]);
            float2 hi = __half22float2(*(__half2*)&sch[nt][1]);
            sc[nt][0] = lo.x; sc[nt][1] = lo.y;
            sc[nt][2] = hi.x; sc[nt][3] = hi.y;
        }

        // online softmax (rows g and g+8; quad-shuffle reductions)
        float rmax0 = -1e30f, rmax1 = -1e30f;
        #pragma unroll
        for (int nt = 0; nt < 8; nt++) {
            #pragma unroll
            for (int j = 0; j < 4; j++) sc[nt][j] *= inv_scale;
            rmax0 = fmaxf(rmax0, fmaxf(sc[nt][0], sc[nt][1]));
            rmax1 = fmaxf(rmax1, fmaxf(sc[nt][2], sc[nt][3]));
        }
        #pragma unroll
        for (int off = 1; off <= 2; off <<= 1) {
            rmax0 = fmaxf(rmax0, __shfl_xor_sync(0xffffffffu, rmax0, off, 4));
            rmax1 = fmaxf(rmax1, __shfl_xor_sync(0xffffffffu, rmax1, off, 4));
        }
        float mn0 = fmaxf(m_i[0], rmax0);
        float mn1 = fmaxf(m_i[1], rmax1);
        float fac0 = __expf(m_i[0] - mn0);
        float fac1 = __expf(m_i[1] - mn1);
        m_i[0] = mn0; m_i[1] = mn1;

        float rs0 = 0.f, rs1 = 0.f;
        #pragma unroll
        for (int nt = 0; nt < 8; nt++) {
            sc[nt][0] = __expf(sc[nt][0] - mn0);
            sc[nt][1] = __expf(sc[nt][1] - mn0);
            sc[nt][2] = __expf(sc[nt][2] - mn1);
            sc[nt][3] = __expf(sc[nt][3] - mn1);
            rs0 += sc[nt][0] + sc[nt][1];
            rs1 += sc[nt][2] + sc[nt][3];
        }
        #pragma unroll
        for (int off = 1; off <= 2; off <<= 1) {
            rs0 += __shfl_xor_sync(0xffffffffu, rs0, off, 4);
            rs1 += __shfl_xor_sync(0xffffffffu, rs1, off, 4);
        }
        l_i[0] = l_i[0] * fac0 + rs0;
        l_i[1] = l_i[1] * fac1 + rs1;
        #pragma unroll
        for (int et = 0; et < 8; et++) {
            o[et][0] *= fac0; o[et][1] *= fac0;
            o[et][2] *= fac1; o[et][3] *= fac1;
        }

        // O += P @ V ; P repacked to A-frags; f32-accumulate (accuracy-critical)
        #pragma unroll
        for (int kst = 0; kst < 4; kst++) {
            uint32_t pa[4] = {
                h2pack(sc[2*kst][0],   sc[2*kst][1]),
                h2pack(sc[2*kst][2],   sc[2*kst][3]),
                h2pack(sc[2*kst+1][0], sc[2*kst+1][1]),
                h2pack(sc[2*kst+1][2], sc[2*kst+1][3])};
            #pragma unroll
            for (int eb = 0; eb < 4; eb++) {
                uint32_t r[4];
                ldsm4t(r, vb + ((kst * 16 + (lane & 15)) * ASTRIDE
                                + eb * 16 + (lane >> 4) * 8) * 2);
                mma16(o[eb * 2],     pa, r[0], r[1]);
                mma16(o[eb * 2 + 1], pa, r[2], r[3]);
            }
        }
    }

    // normalize + store ctx fp16 into [m][768]
    float il0 = 1.0f / l_i[0], il1 = 1.0f / l_i[1];
    int s0 = q0 + wm + g;
    size_t row0 = ((size_t)b * SS + s0) * DD + h * HD;
    #pragma unroll
    for (int et = 0; et < 8; et++) {
        int c = et * 8 + 2 * t4;
        *(__half2*)&g_C[row0 + c] =
            __floats2half2_rn(o[et][0] * il0, o[et][1] * il0);
        *(__half2*)&g_C[row0 + 8 * DD + c] =
            __floats2half2_rn(o[et][2] * il1, o[et][3] * il1);
    }
}

// ---------------------------------------------------------------------------
extern "C" void kernel_launch(void* const* d_in, const int* in_sizes, int n_in,
                              void* d_out, int out_size) {
    const float* x  = (const float*)d_in[0];
    const float* Wq = (const float*)d_in[1];
    const float* bq = (const float*)d_in[2];
    const float* Wk = (const float*)d_in[3];
    const float* bk = (const float*)d_in[4];
    const float* Wv = (const float*)d_in[5];
    const float* bv = (const float*)d_in[6];
    const float* Wp = (const float*)d_in[7];
    const float* bp = (const float*)d_in[8];
    float* out = (float*)d_out;

    prep_x<<<M_ROWS * DD / (8 * 256), 256>>>(x);
    prep_w<<<36, 256>>>(Wq, Wk, Wv);
    prep_wp<<<dim3(DD / 32, DD / 32), 256>>>(Wp);

    qkv_hmma<<<dim3(3 * DD / 128, M_ROWS / 128), 256>>>(bq, bk, bv);

    cudaFuncSetAttribute(attn_hmma, cudaFuncAttributeMaxDynamicSharedMemorySize,
                         ATT_SM_BYTES);
    attn_hmma<<<dim3(SS / 128, BB * HH), 256, ATT_SM_BYTES>>>();

    proj_hmma<<<dim3(DD / 128, M_ROWS / 128), 256>>>(bp, out);
}

// round 14
// speedup vs baseline: 1.0564x; 1.0293x over previous
#include <cuda_runtime.h>
#include <cuda_fp16.h>
#include <math.h>
#include <stdint.h>

#define BB 8
#define SS 2048
#define DD 768
#define HH 12
#define HD 64
#define M_ROWS (BB*SS)

// fp16 scratch (allocation-free __device__ globals)
__device__ __half g_X [M_ROWS*DD];          // x as fp16 [m][k]
__device__ __half g_W [3*DD*DD];            // qkv weights, n-major
__device__ __half g_Wp[DD*DD];              // Wp transposed: [n][k]
__device__ __half g_Q [BB*HH*SS*HD];
__device__ __half g_K [BB*HH*SS*HD];
__device__ __half g_V [BB*HH*SS*HD];
__device__ __half g_C [M_ROWS*DD];          // ctx fp16 [m][h*64+e]

// ---------------------------------------------------------------------------
// primitives
// ---------------------------------------------------------------------------
__device__ __forceinline__ uint32_t smem_u32(const void* p) {
    uint32_t a;
    asm("{ .reg .u64 t; cvta.to.shared.u64 t, %1; cvt.u32.u64 %0, t; }"
        : "=r"(a) : "l"(p));
    return a;
}
__device__ __forceinline__ void cp16(uint32_t dst, const void* src) {
    asm volatile("cp.async.cg.shared.global [%0], [%1], 16;" :: "r"(dst), "l"(src));
}
__device__ __forceinline__ void cp_commit() {
    asm volatile("cp.async.commit_group;" ::: "memory");
}
template<int N> __device__ __forceinline__ void cp_wait() {
    asm volatile("cp.async.wait_group %0;" :: "n"(N) : "memory");
}
__device__ __forceinline__ void ldsm4(uint32_t* r, uint32_t a) {
    asm volatile("ldmatrix.sync.aligned.m8n8.x4.shared.b16 {%0,%1,%2,%3}, [%4];"
        : "=r"(r[0]), "=r"(r[1]), "=r"(r[2]), "=r"(r[3]) : "r"(a));
}
__device__ __forceinline__ void ldsm4t(uint32_t* r, uint32_t a) {
    asm volatile("ldmatrix.sync.aligned.m8n8.x4.trans.shared.b16 {%0,%1,%2,%3}, [%4];"
        : "=r"(r[0]), "=r"(r[1]), "=r"(r[2]), "=r"(r[3]) : "r"(a));
}
// fp32-accumulate HMMA
__device__ __forceinline__ void mma16(float* c, const uint32_t* a,
                                      uint32_t b0, uint32_t b1) {
    asm volatile(
        "mma.sync.aligned.m16n8k16.row.col.f32.f16.f16.f32 "
        "{%0,%1,%2,%3},{%4,%5,%6,%7},{%8,%9},{%0,%1,%2,%3};"
        : "+f"(c[0]), "+f"(c[1]), "+f"(c[2]), "+f"(c[3])
        : "r"(a[0]), "r"(a[1]), "r"(a[2]), "r"(a[3]), "r"(b0), "r"(b1));
}
// fp16-accumulate HMMA (QK^T only)
__device__ __forceinline__ void mma16h(uint32_t* c, const uint32_t* a,
                                       uint32_t b0, uint32_t b1) {
    asm volatile(
        "mma.sync.aligned.m16n8k16.row.col.f16.f16.f16.f16 "
        "{%0,%1},{%2,%3,%4,%5},{%6,%7},{%0,%1};"
        : "+r"(c[0]), "+r"(c[1])
        : "r"(a[0]), "r"(a[1]), "r"(a[2]), "r"(a[3]), "r"(b0), "r"(b1));
}
__device__ __forceinline__ uint32_t h2pack(float a, float b) {
    __half2 h = __floats2half2_rn(a, b);
    return *(uint32_t*)&h;
}

// ---------------------------------------------------------------------------
// prep kernels (fp32 -> fp16, weight transposes)
// ---------------------------------------------------------------------------
__global__ void prep_x(const float* __restrict__ x) {
    size_t idx = (size_t)blockIdx.x * 256 + threadIdx.x;
    const float4* s = (const float4*)x + idx * 2;
    float4 v0 = s[0], v1 = s[1];
    __half2 h0 = __floats2half2_rn(v0.x, v0.y);
    __half2 h1 = __floats2half2_rn(v0.z, v0.w);
    __half2 h2 = __floats2half2_rn(v1.x, v1.y);
    __half2 h3 = __floats2half2_rn(v1.z, v1.w);
    uint4 u;
    u.x = *(uint32_t*)&h0; u.y = *(uint32_t*)&h1;
    u.z = *(uint32_t*)&h2; u.w = *(uint32_t*)&h3;
    *(uint4*)&g_X[idx * 8] = u;
}

__global__ void prep_w(const float* __restrict__ Wq, const float* __restrict__ Wk,
                       const float* __restrict__ Wv) {
    int mh = blockIdx.x;
    int mat = mh / HH, h = mh % HH;
    const float* W = (mat == 0 ? Wq : mat == 1 ? Wk : Wv) + (size_t)h * DD * HD;
    __half* dst = g_W + ((size_t)mat * DD + h * HD) * DD;
    __shared__ float tile[32][HD + 1];
    int tid = threadIdx.x;
    for (int k0 = 0; k0 < DD; k0 += 32) {
        __syncthreads();
        #pragma unroll
        for (int it = 0; it < 8; it++) {
            int idx = tid + it * 256;
            int k = idx >> 6, e = idx & 63;
            tile[k][e] = W[(size_t)(k0 + k) * HD + e];
        }
        __syncthreads();
        #pragma unroll
        for (int it = 0; it < 8; it++) {
            int idx = tid + it * 256;
            int e = idx >> 5, k = idx & 31;
            dst[(size_t)e * DD + k0 + k] = __float2half(tile[k][e]);
        }
    }
}

__global__ void prep_wp(const float* __restrict__ Wp) {
    int n0 = blockIdx.x * 32, k0 = blockIdx.y * 32;
    __shared__ float tile[32][33];
    int tid = threadIdx.x;
    #pragma unroll
    for (int it = 0; it < 4; it++) {
        int idx = tid + it * 256;
        int k = idx >> 5, n = idx & 31;
        tile[k][n] = Wp[(size_t)(k0 + k) * DD + n0 + n];
    }
    __syncthreads();
    #pragma unroll
    for (int it = 0; it < 4; it++) {
        int idx = tid + it * 256;
        int n = idx >> 5, k = idx & 31;
        g_Wp[(size_t)(n0 + n) * DD + k0 + k] = __float2half(tile[k][n]);
    }
}

// ---------------------------------------------------------------------------
// Attention-style GEMM: block = 128 M x 128 N. 8 warps; warp w owns rows
// [16w,16w+16) x all 128 N. K streamed in 12 chunks of 64 via a 3-STAGE
// cp.async ring (prefetch distance 2, buffers mod 3 — attention's proven
// scheme), ONE __syncthreads per chunk. Per chunk per warp: 4 A-LDSM
// (register-held, reused 8x), 32 B-LDSM, 64 HMMA. Row stride 72 halves.
// ---------------------------------------------------------------------------
#define GKSTRIDE 72
#define GKTILE (128 * GKSTRIDE)            // halves per (A or B) stage tile
#define GEMM_SM_BYTES (6 * GKTILE * 2)     // 3 stages x (A+B) = 110592 B

// stage chunk t (64 k) of A[128][DD], B[128][DD] into stride-72 smem
__device__ __forceinline__ void gk_stage(uint32_t aB, uint32_t bB,
                                         const __half* Ag, const __half* Bg,
                                         int t, int tid) {
    #pragma unroll
    for (int it = 0; it < 4; it++) {
        int idx = tid + it * 256;
        int r = idx >> 3, s = idx & 7;
        cp16(aB + (r * GKSTRIDE + s * 8) * 2, Ag + (size_t)r * DD + t * 64 + s * 8);
    }
    #pragma unroll
    for (int it = 0; it < 4; it++) {
        int idx = tid + it * 256;
        int r = idx >> 3, s = idx & 7;
        cp16(bB + (r * GKSTRIDE + s * 8) * 2, Bg + (size_t)r * DD + t * 64 + s * 8);
    }
    cp_commit();
}

// One K-chunk of compute: A frags loaded once, B streamed (attn-QK shape).
__device__ __forceinline__ void gk_compute(uint32_t aB, uint32_t bB,
                                           int lane, int wm,
                                           float acc[16][4]) {
    uint32_t a[4][4];
    #pragma unroll
    for (int kst = 0; kst < 4; kst++)
        ldsm4(a[kst], aB + ((wm + (lane & 15)) * GKSTRIDE
                            + kst * 16 + (lane >> 4) * 8) * 2);
    #pragma unroll
    for (int kst = 0; kst < 4; kst++) {
        #pragma unroll
        for (int np = 0; np < 8; np++) {
            uint32_t r[4];
            ldsm4(r, bB + ((np * 16 + (lane & 15)) * GKSTRIDE
                           + kst * 16 + (lane >> 4) * 8) * 2);
            mma16(acc[np * 2],     a[kst], r[0], r[2]);
            mma16(acc[np * 2 + 1], a[kst], r[1], r[3]);
        }
    }
}

// 3-stage ring, distance 2 (buffer (t+2)%3 never collides with t or t+1).
// The top-of-loop __syncthreads at iter t+1 orders all compute of chunk t
// before the staging of chunk t+3 into buffer t%3.
#define GK_MAINLOOP(Ag, Bg)                                                    \
    uint32_t base = smem_u32(dynsm);                                           \
    uint32_t aS[3], bS[3];                                                     \
    _Pragma("unroll")                                                          \
    for (int s = 0; s < 3; s++) {                                              \
        aS[s] = base + (2 * s) * GKTILE * 2;                                   \
        bS[s] = base + (2 * s + 1) * GKTILE * 2;                               \
    }                                                                          \
    float acc[16][4] = {};                                                     \
    gk_stage(aS[0], bS[0], Ag, Bg, 0, tid);                                    \
    gk_stage(aS[1], bS[1], Ag, Bg, 1, tid);                                    \
    for (int t = 0; t < 12; t++) {                                             \
        cp_wait<1>();                                                          \
        __syncthreads();                                                       \
        if (t + 2 < 12) gk_stage(aS[(t+2)%3], bS[(t+2)%3], Ag, Bg, t + 2, tid);\
        else cp_commit();                                                      \
        gk_compute(aS[t % 3], bS[t % 3], lane, wm, acc);                       \
    }

// ---------------------------------------------------------------------------
// Kernel 1: fused QKV GEMM. C[16384, 2304] = X @ Wn^T. Grid (18, 128).
// ---------------------------------------------------------------------------
__global__ __launch_bounds__(256)
void qkv_hmma(const float* __restrict__ bq, const float* __restrict__ bk,
              const float* __restrict__ bv) {
    extern __shared__ __half dynsm[];
    int bx = blockIdx.x;
    int m0 = blockIdx.y * 128;
    int tid = threadIdx.x, warp = tid >> 5, lane = tid & 31;
    int g = lane >> 2, t4 = lane & 3;
    int wm = warp * 16;

    const __half* Ag = g_X + (size_t)m0 * DD;
    const __half* Bg = g_W + (size_t)bx * 128 * DD;

    GK_MAINLOOP(Ag, Bg)

    #pragma unroll
    for (int nt = 0; nt < 16; nt++) {
        int n_glob = bx * 128 + nt * 8 + 2 * t4;
        int matIdx = n_glob / DD;
        int rem    = n_glob % DD;
        int h = rem >> 6, e = rem & 63;
        __half* Out = matIdx == 0 ? g_Q : matIdx == 1 ? g_K : g_V;
        const float* bias = matIdx == 0 ? bq : matIdx == 1 ? bk : bv;
        float2 bb = *(const float2*)&bias[h * HD + e];
        int m = m0 + wm + g;
        int b = m >> 11, s = m & 2047;
        size_t base0 = (((size_t)b * HH + h) * SS + s) * HD + e;
        *(__half2*)&Out[base0] =
            __floats2half2_rn(acc[nt][0] + bb.x, acc[nt][1] + bb.y);
        *(__half2*)&Out[base0 + 8 * HD] =
            __floats2half2_rn(acc[nt][2] + bb.x, acc[nt][3] + bb.y);
    }
}

// ---------------------------------------------------------------------------
// Kernel 3: output projection. out[16384, 768] = ctx @ Wp^T + bp. Grid (6, 128).
// ---------------------------------------------------------------------------
__global__ __launch_bounds__(256)
void proj_hmma(const float* __restrict__ bp, float* __restrict__ out) {
    extern __shared__ __half dynsm[];
    int n0 = blockIdx.x * 128;
    int m0 = blockIdx.y * 128;
    int tid = threadIdx.x, warp = tid >> 5, lane = tid & 31;
    int g = lane >> 2, t4 = lane & 3;
    int wm = warp * 16;

    const __half* Ag = g_C + (size_t)m0 * DD;
    const __half* Bg = g_Wp + (size_t)n0 * DD;

    GK_MAINLOOP(Ag, Bg)

    #pragma unroll
    for (int nt = 0; nt < 16; nt++) {
        int n = n0 + nt * 8 + 2 * t4;
        float2 bb = *(const float2*)&bp[n];
        int m = m0 + wm + g;
        float2 o0 = {acc[nt][0] + bb.x, acc[nt][1] + bb.y};
        float2 o1 = {acc[nt][2] + bb.x, acc[nt][3] + bb.y};
        *(float2*)&out[(size_t)m * DD + n]       = o0;
        *(float2*)&out[(size_t)(m + 8) * DD + n] = o1;
    }
}

// ---------------------------------------------------------------------------
// Kernel 2: flash attention (unchanged from Round 11 — near tensor floor).
// BR=128, BC=64, 8 warps x 16 q-rows. QK^T f16-accum; PV f32-accum.
// ---------------------------------------------------------------------------
#define ASTRIDE 72
#define KVSZ (64 * ASTRIDE)
#define ATT_SM_BYTES ((128 * ASTRIDE + 6 * KVSZ) * 2)

__global__ __launch_bounds__(256, 2)
void attn_hmma() {
    extern __shared__ __half sh[];
    __half* Qs = sh;                    // 128 x 72
    __half* Ks = sh + 128 * ASTRIDE;    // 3 x 64 x 72
    __half* Vs = Ks + 3 * KVSZ;         // 3 x 64 x 72

    int bh = blockIdx.y, q0 = blockIdx.x * 128;
    const __half* Qg = g_Q + (size_t)bh * SS * HD;
    const __half* Kg = g_K + (size_t)bh * SS * HD;
    const __half* Vg = g_V + (size_t)bh * SS * HD;
    int b = bh / HH, h = bh % HH;

    int tid = threadIdx.x, warp = tid >> 5, lane = tid & 31;
    int g = lane >> 2, t4 = lane & 3;
    int wm = warp * 16;

    uint32_t qB = smem_u32(Qs), kB = smem_u32(Ks), vB = smem_u32(Vs);

    #pragma unroll
    for (int it = 0; it < 4; it++) {
        int idx = tid + it * 256;
        int r = idx >> 3, s = idx & 7;
        cp16(qB + (r * ASTRIDE + s * 8) * 2, Qg + (size_t)(q0 + r) * HD + s * 8);
    }
    cp_commit();

    #define STAGE_KV(kc, buf) do {                                              \
        const __half* Ksrc = Kg + (size_t)(kc) * 64 * HD;                       \
        const __half* Vsrc = Vg + (size_t)(kc) * 64 * HD;                       \
        uint32_t kd = kB + (buf) * KVSZ * 2, vd = vB + (buf) * KVSZ * 2;        \
        _Pragma("unroll")                                                       \
        for (int it = 0; it < 2; it++) {                                        \
            int idx = tid + it * 256;                                           \
            int r = idx >> 3, s = idx & 7;                                      \
            cp16(kd + (r * ASTRIDE + s * 8) * 2, Ksrc + (size_t)r * HD + s * 8);\
            cp16(vd + (r * ASTRIDE + s * 8) * 2, Vsrc + (size_t)r * HD + s * 8);\
        }                                                                       \
        cp_commit();                                                            \
    } while (0)

    STAGE_KV(0, 0);
    STAGE_KV(1, 1);

    cp_wait<2>();
    __syncthreads();

    uint32_t qa[4][4];
    #pragma unroll
    for (int kst = 0; kst < 4; kst++)
        ldsm4(qa[kst], qB + ((wm + (lane & 15)) * ASTRIDE
                             + kst * 16 + (lane >> 4) * 8) * 2);

    float o[8][4] = {};
    float m_i[2] = {-1e30f, -1e30f};
    float l_i[2] = {0.f, 0.f};
    const float inv_scale = 1.0f / (8.0f + 1e-6f);   // 1/(sqrt(64)+EPS)

    for (int kc = 0; kc < 32; kc++) {
        cp_wait<1>();
        __syncthreads();
        if (kc + 2 < 32) STAGE_KV(kc + 2, (kc + 2) % 3);
        else cp_commit();

        int bf = kc % 3;
        uint32_t kb = kB + bf * KVSZ * 2;
        uint32_t vb = vB + bf * KVSZ * 2;

        uint32_t sch[8][2];
        #pragma unroll
        for (int nt = 0; nt < 8; nt++) { sch[nt][0] = 0u; sch[nt][1] = 0u; }
        #pragma unroll
        for (int kst = 0; kst < 4; kst++) {
            #pragma unroll
            for (int cp = 0; cp < 4; cp++) {
                uint32_t r[4];
                ldsm4(r, kb + ((cp * 16 + (lane & 15)) * ASTRIDE
                               + kst * 16 + (lane >> 4) * 8) * 2);
                mma16h(sch[cp * 2],     qa[kst], r[0], r[2]);
                mma16h(sch[cp * 2 + 1], qa[kst], r[1], r[3]);
            }
        }
        float sc[8][4];
        #pragma unroll
        for (int nt = 0; nt < 8; nt++) {
            float2 lo = __half22float2(*(__half2*)&sch[nt][0]);
            float2 hi = __half22float2(*(__half2*)&sch[nt][1]);
            sc[nt][0] = lo.x; sc[nt][1] = lo.y;
            sc[nt][2] = hi.x; sc[nt][3] = hi.y;
        }

        float rmax0 = -1e30f, rmax1 = -1e30f;
        #pragma unroll
        for (int nt = 0; nt < 8; nt++) {
            #pragma unroll
            for (int j = 0; j < 4; j++) sc[nt][j] *= inv_scale;
            rmax0 = fmaxf(rmax0, fmaxf(sc[nt][0], sc[nt][1]));
            rmax1 = fmaxf(rmax1, fmaxf(sc[nt][2], sc[nt][3]));
        }
        #pragma unroll
        for (int off = 1; off <= 2; off <<= 1) {
            rmax0 = fmaxf(rmax0, __shfl_xor_sync(0xffffffffu, rmax0, off, 4));
            rmax1 = fmaxf(rmax1, __shfl_xor_sync(0xffffffffu, rmax1, off, 4));
        }
        float mn0 = fmaxf(m_i[0], rmax0);
        float mn1 = fmaxf(m_i[1], rmax1);
        float fac0 = __expf(m_i[0] - mn0);
        float fac1 = __expf(m_i[1] - mn1);
        m_i[0] = mn0; m_i[1] = mn1;

        float rs0 = 0.f, rs1 = 0.f;
        #pragma unroll
        for (int nt = 0; nt < 8; nt++) {
            sc[nt][0] = __expf(sc[nt][0] - mn0);
            sc[nt][1] = __expf(sc[nt][1] - mn0);
            sc[nt][2] = __expf(sc[nt][2] - mn1);
            sc[nt][3] = __expf(sc[nt][3] - mn1);
            rs0 += sc[nt][0] + sc[nt][1];
            rs1 += sc[nt][2] + sc[nt][3];
        }
        #pragma unroll
        for (int off = 1; off <= 2; off <<= 1) {
            rs0 += __shfl_xor_sync(0xffffffffu, rs0, off, 4);
            rs1 += __shfl_xor_sync(0xffffffffu, rs1, off, 4);
        }
        l_i[0] = l_i[0] * fac0 + rs0;
        l_i[1] = l_i[1] * fac1 + rs1;
        #pragma unroll
        for (int et = 0; et < 8; et++) {
            o[et][0] *= fac0; o[et][1] *= fac0;
            o[et][2] *= fac1; o[et][3] *= fac1;
        }

        #pragma unroll
        for (int kst = 0; kst < 4; kst++) {
            uint32_t pa[4] = {
                h2pack(sc[2*kst][0],   sc[2*kst][1]),
                h2pack(sc[2*kst][2],   sc[2*kst][3]),
                h2pack(sc[2*kst+1][0], sc[2*kst+1][1]),
                h2pack(sc[2*kst+1][2], sc[2*kst+1][3])};
            #pragma unroll
            for (int eb = 0; eb < 4; eb++) {
                uint32_t r[4];
                ldsm4t(r, vb + ((kst * 16 + (lane & 15)) * ASTRIDE
                                + eb * 16 + (lane >> 4) * 8) * 2);
                mma16(o[eb * 2],     pa, r[0], r[1]);
                mma16(o[eb * 2 + 1], pa, r[2], r[3]);
            }
        }
    }

    float il0 = 1.0f / l_i[0], il1 = 1.0f / l_i[1];
    int s0 = q0 + wm + g;
    size_t row0 = ((size_t)b * SS + s0) * DD + h * HD;
    #pragma unroll
    for (int et = 0; et < 8; et++) {
        int c = et * 8 + 2 * t4;
        *(__half2*)&g_C[row0 + c] =
            __floats2half2_rn(o[et][0] * il0, o[et][1] * il0);
        *(__half2*)&g_C[row0 + 8 * DD + c] =
            __floats2half2_rn(o[et][2] * il1, o[et][3] * il1);
    }
}

// ---------------------------------------------------------------------------
extern "C" void kernel_launch(void* const* d_in, const int* in_sizes, int n_in,
                              void* d_out, int out_size) {
    const float* x  = (const float*)d_in[0];
    const float* Wq = (const float*)d_in[1];
    const float* bq = (const float*)d_in[2];
    const float* Wk = (const float*)d_in[3];
    const float* bk = (const float*)d_in[4];
    const float* Wv = (const float*)d_in[5];
    const float* bv = (const float*)d_in[6];
    const float* Wp = (const float*)d_in[7];
    const float* bp = (const float*)d_in[8];
    float* out = (float*)d_out;

    prep_x<<<M_ROWS * DD / (8 * 256), 256>>>(x);
    prep_w<<<36, 256>>>(Wq, Wk, Wv);
    prep_wp<<<dim3(DD / 32, DD / 32), 256>>>(Wp);

    cudaFuncSetAttribute(qkv_hmma, cudaFuncAttributeMaxDynamicSharedMemorySize,
                         GEMM_SM_BYTES);
    qkv_hmma<<<dim3(3 * DD / 128, M_ROWS / 128), 256, GEMM_SM_BYTES>>>(bq, bk, bv);

    cudaFuncSetAttribute(attn_hmma, cudaFuncAttributeMaxDynamicSharedMemorySize,
                         ATT_SM_BYTES);
    attn_hmma<<<dim3(SS / 128, BB * HH), 256, ATT_SM_BYTES>>>();

    cudaFuncSetAttribute(proj_hmma, cudaFuncAttributeMaxDynamicSharedMemorySize,
                         GEMM_SM_BYTES);
    proj_hmma<<<dim3(DD / 128, M_ROWS / 128), 256, GEMM_SM_BYTES>>>(bp, out);
}